// round 7
// baseline (speedup 1.0000x reference)
#include <cuda_runtime.h>

// SparseAudioModel gather:
//   out[b, s] = sum_e x[b, e, s - time_e],  time_e = idx[b,e]*256, active iff time_e <= s
//
// R7 = R5 (mirror-pair tiles + batched predicated loads) with:
//  - LDG.128 (float4): 512B per warp request instead of 256B (halve request
//    count per byte through L1tex/LTS),
//  - ld.global.nc.L2::256B: non-coherent path + 256B L2 fetch hint (deeper
//    DRAM bursts for the 64-stream interleaved pattern).
// Tiles are 512 samples (128 thr x float4); block does tile k and 63-k so
// per-block bytes are uniform (~66KB); 512 blocks all co-resident.

#define N_SAMPLES 32768
#define N_EVENTS  64
#define STEP_SIZE 256
#define BATCH     16
#define TILE      512                 // 128 threads * float4
#define NTILES    (N_SAMPLES / TILE)  // 64
#define GRP       8                   // events per software-pipelined batch

__global__ __launch_bounds__(128) void sparse_audio_gather(
    const float* __restrict__ x,      // [B, E, S]
    const int*   __restrict__ idx,    // [B, E]
    float*       __restrict__ out)    // [B, S]
{
    __shared__ int s_time[N_EVENTS];

    const int k = blockIdx.x;         // tile pair id 0..31
    const int b = blockIdx.y;
    const int t = threadIdx.x;

    if (t < N_EVENTS)
        s_time[t] = idx[b * N_EVENTS + t] * STEP_SIZE;
    __syncthreads();

    const int s_lo = k * TILE + t * 4;                 // light tile sample
    const int s_hi = (NTILES - 1 - k) * TILE + t * 4;  // heavy tile sample

    const float* xb = x + (size_t)b * N_EVENTS * N_SAMPLES;

    float4 al = make_float4(0.f, 0.f, 0.f, 0.f);
    float4 ah = make_float4(0.f, 0.f, 0.f, 0.f);

    #pragma unroll
    for (int g = 0; g < N_EVENTS; g += GRP) {
        float4 vl[GRP], vh[GRP];

        // ---- issue 16 predicated LDG.128, no consumption yet ----
        #pragma unroll
        for (int j = 0; j < GRP; ++j) {
            const int e    = g + j;
            const int time = s_time[e];
            const float* pe = xb + (size_t)e * N_SAMPLES - time;

            vl[j] = make_float4(0.f, 0.f, 0.f, 0.f);
            vh[j] = make_float4(0.f, 0.f, 0.f, 0.f);

            asm("{\n\t"
                ".reg .pred p;\n\t"
                "setp.le.s32 p, %4, %5;\n\t"
                "@p ld.global.nc.L2::256B.v4.f32 {%0, %1, %2, %3}, [%6];\n\t"
                "}"
                : "+f"(vl[j].x), "+f"(vl[j].y), "+f"(vl[j].z), "+f"(vl[j].w)
                : "r"(time), "r"(s_lo), "l"(pe + s_lo));

            asm("{\n\t"
                ".reg .pred p;\n\t"
                "setp.le.s32 p, %4, %5;\n\t"
                "@p ld.global.nc.L2::256B.v4.f32 {%0, %1, %2, %3}, [%6];\n\t"
                "}"
                : "+f"(vh[j].x), "+f"(vh[j].y), "+f"(vh[j].z), "+f"(vh[j].w)
                : "r"(time), "r"(s_hi), "l"(pe + s_hi));
        }

        // ---- consume ----
        #pragma unroll
        for (int j = 0; j < GRP; ++j) {
            al.x += vl[j].x; al.y += vl[j].y; al.z += vl[j].z; al.w += vl[j].w;
            ah.x += vh[j].x; ah.y += vh[j].y; ah.z += vh[j].z; ah.w += vh[j].w;
        }
    }

    float* ob = out + (size_t)b * N_SAMPLES;
    asm("st.global.cs.v4.f32 [%0], {%1, %2, %3, %4};"
        :: "l"(ob + s_lo), "f"(al.x), "f"(al.y), "f"(al.z), "f"(al.w) : "memory");
    asm("st.global.cs.v4.f32 [%0], {%1, %2, %3, %4};"
        :: "l"(ob + s_hi), "f"(ah.x), "f"(ah.y), "f"(ah.z), "f"(ah.w) : "memory");
}

extern "C" void kernel_launch(void* const* d_in, const int* in_sizes, int n_in,
                              void* d_out, int out_size)
{
    const float* x   = (const float*)d_in[0];   // [16, 64, 32768] float32
    const int*   idx = (const int*)  d_in[1];   // [16, 64] int32
    float*       out = (float*)d_out;           // [16, 1, 32768] float32

    dim3 block(128);
    dim3 grid(NTILES / 2, BATCH);               // (32, 16) = 512 blocks
    sparse_audio_gather<<<grid, block>>>(x, idx, out);
}

// round 8
// speedup vs baseline: 1.2457x; 1.2457x over previous
#include <cuda_runtime.h>
#include <cstdint>

// SparseAudioModel gather:
//   out[b, s] = sum_e x[b, e, s - time_e],  time_e = idx[b,e]*256, active iff time_e <= s
//
// R8: cp.async.cg staging, barrier-free. Each thread owns bytes [16t,16t+16)
// of every staged event slab: it issues the copy AND reads it back, so
// cp.async.wait_group alone gives visibility (no block syncs in the loop).
// Inactive events use src-size=0 zero-fill (clamped in-bounds address), so the
// 64-event loop is static and branch-free. In-flight depth = 4 groups x 4
// events x 16B = 256B/thread at ~zero register cost.

#define S_SAMP  32768
#define N_EV    64
#define STEP    256
#define NBATCH  16
#define TILE    512                   // samples per block: 128 thr * float4
#define NT      (S_SAMP / TILE)       // 64
#define G       4                     // events per stage
#define NSTG    4                     // ring slots
#define NGRP    (N_EV / G)            // 16 stages

__device__ __forceinline__ uint32_t s2u(const void* p) {
    uint32_t a;
    asm("{ .reg .u64 t; cvta.to.shared.u64 t, %1; cvt.u32.u64 %0, t; }"
        : "=r"(a) : "l"(p));
    return a;
}

__global__ __launch_bounds__(128) void sparse_audio_cpasync(
    const float* __restrict__ x,      // [B, E, S]
    const int*   __restrict__ idx,    // [B, E]
    float*       __restrict__ out)    // [B, S]
{
    __shared__ int s_time[N_EV];
    __shared__ alignas(16) float buf[NSTG][G][TILE];   // 32 KB ring

    const int t = threadIdx.x;
    const int k = blockIdx.x;
    const int b = blockIdx.y;

    if (t < N_EV)
        s_time[t] = idx[b * N_EV + t] * STEP;
    __syncthreads();

    const int s4 = k * TILE + t * 4;              // this thread's 4 samples
    const float* xb = x + (size_t)b * N_EV * S_SAMP;
    const uint32_t my_smem = s2u(&buf[0][0][t * 4]);   // +slot*G*2KB +g*2KB

    // Issue one stage: 4 cp.async (16B each), zero-filled when inactive.
    auto issue = [&](int stg) {
        const int slot = stg & (NSTG - 1);
        #pragma unroll
        for (int g = 0; g < G; ++g) {
            const int e    = stg * G + g;
            const int time = s_time[e];
            const bool act = (time <= s4);
            const float* src = xb + (size_t)e * S_SAMP + (act ? (s4 - time) : 0);
            const int sz = act ? 16 : 0;          // 0 => full zero-fill
            const uint32_t dst = my_smem + (slot * G + g) * (TILE * 4);
            asm volatile("cp.async.cg.shared.global [%0], [%1], 16, %2;"
                         :: "r"(dst), "l"(src), "r"(sz) : "memory");
        }
        asm volatile("cp.async.commit_group;" ::: "memory");
    };

    // Prologue: fill 3 stages.
    issue(0); issue(1); issue(2);

    float4 acc = make_float4(0.f, 0.f, 0.f, 0.f);

    #pragma unroll 4
    for (int j = 0; j < NGRP; ++j) {
        if (j + 3 < NGRP) {
            issue(j + 3);
        } else {
            // empty group keeps "total groups = j+4" so wait_group 3 always
            // guarantees group j is complete
            asm volatile("cp.async.commit_group;" ::: "memory");
        }
        asm volatile("cp.async.wait_group 3;" ::: "memory");

        const int slot = j & (NSTG - 1);
        #pragma unroll
        for (int g = 0; g < G; ++g) {
            const float4 v = *reinterpret_cast<const float4*>(
                &buf[slot][g][t * 4]);
            acc.x += v.x; acc.y += v.y; acc.z += v.z; acc.w += v.w;
        }
    }

    asm("st.global.cs.v4.f32 [%0], {%1, %2, %3, %4};"
        :: "l"(out + (size_t)b * S_SAMP + s4),
           "f"(acc.x), "f"(acc.y), "f"(acc.z), "f"(acc.w) : "memory");
}

extern "C" void kernel_launch(void* const* d_in, const int* in_sizes, int n_in,
                              void* d_out, int out_size)
{
    const float* x   = (const float*)d_in[0];   // [16, 64, 32768] float32
    const int*   idx = (const int*)  d_in[1];   // [16, 64] int32
    float*       out = (float*)d_out;           // [16, 1, 32768] float32

    // Maximize shared-memory carveout so 7 blocks/SM fit (32KB each).
    static cudaError_t _attr_rc = cudaFuncSetAttribute(
        sparse_audio_cpasync,
        cudaFuncAttributePreferredSharedMemoryCarveout, 100);
    (void)_attr_rc;

    dim3 block(128);
    dim3 grid(NT, NBATCH);                      // (64, 16) = 1024 blocks
    sparse_audio_cpasync<<<grid, block>>>(x, idx, out);
}

// round 9
// speedup vs baseline: 1.8000x; 1.4450x over previous
#include <cuda_runtime.h>

// SparseAudioModel gather:
//   out[b, s] = sum_e x[b, e, s - time_e],  time_e = idx[b,e]*256, active iff time_e <= s
//
// R9 = R5 (best: 12.8us) with the register cap lifted:
//  - __launch_bounds__(128, 6): allows ~85 regs/thread so ptxas can hold the
//    full load batch in flight (R5 clamped to 44 regs ≈ 10 held loads).
//  - GRP=16: 32 predicated float2 loads issued per group before any FADD.
// Everything else proven: mirror-pair tiles (uniform ~65 loads/block),
// 1024 co-resident 128-thread blocks, .cs streaming loads/stores.
//
// Model: steady-state is at the HBM ceiling (~6.5-6.8 TB/s); timed 12.8us =
// ~10us memory + ~2.7us fixed launch/ramp/drain. This round confirms whether
// any reg-capped MLP slack remains.

#define N_SAMPLES 32768
#define N_EVENTS  64
#define STEP_SIZE 256
#define BATCH     16
#define TILE      256                 // one tile = 128 threads * float2
#define NTILES    (N_SAMPLES / TILE)  // 128
#define GRP       16

__global__ __launch_bounds__(128, 6) void sparse_audio_gather(
    const float* __restrict__ x,      // [B, E, S]
    const int*   __restrict__ idx,    // [B, E]
    float*       __restrict__ out)    // [B, S]
{
    __shared__ int s_time[N_EVENTS];

    const int k = blockIdx.x;         // tile pair id 0..63
    const int b = blockIdx.y;
    const int t = threadIdx.x;

    if (t < N_EVENTS)
        s_time[t] = idx[b * N_EVENTS + t] * STEP_SIZE;
    __syncthreads();

    const int s_lo = k * TILE + t * 2;                 // light tile
    const int s_hi = (NTILES - 1 - k) * TILE + t * 2;  // heavy tile

    const float* xb = x + (size_t)b * N_EVENTS * N_SAMPLES;

    float alx = 0.f, aly = 0.f;       // lo-tile accumulator
    float ahx = 0.f, ahy = 0.f;       // hi-tile accumulator

    #pragma unroll
    for (int g = 0; g < N_EVENTS; g += GRP) {
        float vlx[GRP], vly[GRP], vhx[GRP], vhy[GRP];

        // ---- issue 32 predicated loads, no consumption yet ----
        #pragma unroll
        for (int j = 0; j < GRP; ++j) {
            const int e    = g + j;
            const int time = s_time[e];
            const float* pe = xb + (size_t)e * N_SAMPLES - time;

            vlx[j] = 0.f; vly[j] = 0.f;
            vhx[j] = 0.f; vhy[j] = 0.f;

            asm("{\n\t"
                ".reg .pred p;\n\t"
                "setp.le.s32 p, %2, %3;\n\t"
                "@p ld.global.cs.v2.f32 {%0, %1}, [%4];\n\t"
                "}"
                : "+f"(vlx[j]), "+f"(vly[j])
                : "r"(time), "r"(s_lo), "l"(pe + s_lo));

            asm("{\n\t"
                ".reg .pred p;\n\t"
                "setp.le.s32 p, %2, %3;\n\t"
                "@p ld.global.cs.v2.f32 {%0, %1}, [%4];\n\t"
                "}"
                : "+f"(vhx[j]), "+f"(vhy[j])
                : "r"(time), "r"(s_hi), "l"(pe + s_hi));
        }

        // ---- consume ----
        #pragma unroll
        for (int j = 0; j < GRP; ++j) {
            alx += vlx[j]; aly += vly[j];
            ahx += vhx[j]; ahy += vhy[j];
        }
    }

    float* ob = out + (size_t)b * N_SAMPLES;
    asm("st.global.cs.v2.f32 [%0], {%1, %2};"
        :: "l"(ob + s_lo), "f"(alx), "f"(aly) : "memory");
    asm("st.global.cs.v2.f32 [%0], {%1, %2};"
        :: "l"(ob + s_hi), "f"(ahx), "f"(ahy) : "memory");
}

extern "C" void kernel_launch(void* const* d_in, const int* in_sizes, int n_in,
                              void* d_out, int out_size)
{
    const float* x   = (const float*)d_in[0];   // [16, 64, 32768] float32
    const int*   idx = (const int*)  d_in[1];   // [16, 64] int32
    float*       out = (float*)d_out;           // [16, 1, 32768] float32

    dim3 block(128);
    dim3 grid(NTILES / 2, BATCH);               // (64, 16) = 1024 blocks
    sparse_audio_gather<<<grid, block>>>(x, idx, out);
}

// round 10
// speedup vs baseline: 2.1053x; 1.1696x over previous
#include <cuda_runtime.h>

// SparseAudioModel gather:
//   out[b, s] = sum_e x[b, e, s - time_e],  time_e = idx[b,e]*256, active iff time_e <= s
//
// R10 = R9 skeleton (mirror-pair tiles, software-pipelined predicated batch,
// .cs streaming, one co-resident wave) with float4 loads instead of float2:
//   - 512B per warp-visit of each event stream (vs 256B): halves the
//     warp-request count per byte and doubles DRAM row-touch per visit.
//   - __launch_bounds__(128, 6) is what R7 (the failed float4 attempt) was
//     missing: R9 proved it lets ptxas hold an 80-reg load batch instead of
//     clamping to 32 regs and serializing.
// GRP=8 events x 2 tiles = 16 LDG.128 in flight per thread (64 data regs).

#define N_SAMPLES 32768
#define N_EVENTS  64
#define STEP_SIZE 256
#define BATCH     16
#define TILE      512                 // one tile = 128 threads * float4
#define NTILES    (N_SAMPLES / TILE)  // 64
#define GRP       8

__global__ __launch_bounds__(128, 6) void sparse_audio_gather(
    const float* __restrict__ x,      // [B, E, S]
    const int*   __restrict__ idx,    // [B, E]
    float*       __restrict__ out)    // [B, S]
{
    __shared__ int s_time[N_EVENTS];

    const int k = blockIdx.x;         // tile pair id 0..31
    const int b = blockIdx.y;
    const int t = threadIdx.x;

    if (t < N_EVENTS)
        s_time[t] = idx[b * N_EVENTS + t] * STEP_SIZE;
    __syncthreads();

    const int s_lo = k * TILE + t * 4;                 // light tile
    const int s_hi = (NTILES - 1 - k) * TILE + t * 4;  // heavy tile

    const float* xb = x + (size_t)b * N_EVENTS * N_SAMPLES;

    float4 al = make_float4(0.f, 0.f, 0.f, 0.f);
    float4 ah = make_float4(0.f, 0.f, 0.f, 0.f);

    #pragma unroll
    for (int g = 0; g < N_EVENTS; g += GRP) {
        float4 vl[GRP], vh[GRP];

        // ---- issue 16 predicated LDG.128, no consumption yet ----
        #pragma unroll
        for (int j = 0; j < GRP; ++j) {
            const int e    = g + j;
            const int time = s_time[e];
            const float* pe = xb + (size_t)e * N_SAMPLES - time;

            vl[j] = make_float4(0.f, 0.f, 0.f, 0.f);
            vh[j] = make_float4(0.f, 0.f, 0.f, 0.f);

            asm("{\n\t"
                ".reg .pred p;\n\t"
                "setp.le.s32 p, %4, %5;\n\t"
                "@p ld.global.cs.v4.f32 {%0, %1, %2, %3}, [%6];\n\t"
                "}"
                : "+f"(vl[j].x), "+f"(vl[j].y), "+f"(vl[j].z), "+f"(vl[j].w)
                : "r"(time), "r"(s_lo), "l"(pe + s_lo));

            asm("{\n\t"
                ".reg .pred p;\n\t"
                "setp.le.s32 p, %4, %5;\n\t"
                "@p ld.global.cs.v4.f32 {%0, %1, %2, %3}, [%6];\n\t"
                "}"
                : "+f"(vh[j].x), "+f"(vh[j].y), "+f"(vh[j].z), "+f"(vh[j].w)
                : "r"(time), "r"(s_hi), "l"(pe + s_hi));
        }

        // ---- consume ----
        #pragma unroll
        for (int j = 0; j < GRP; ++j) {
            al.x += vl[j].x; al.y += vl[j].y; al.z += vl[j].z; al.w += vl[j].w;
            ah.x += vh[j].x; ah.y += vh[j].y; ah.z += vh[j].z; ah.w += vh[j].w;
        }
    }

    float* ob = out + (size_t)b * N_SAMPLES;
    asm("st.global.cs.v4.f32 [%0], {%1, %2, %3, %4};"
        :: "l"(ob + s_lo), "f"(al.x), "f"(al.y), "f"(al.z), "f"(al.w) : "memory");
    asm("st.global.cs.v4.f32 [%0], {%1, %2, %3, %4};"
        :: "l"(ob + s_hi), "f"(ah.x), "f"(ah.y), "f"(ah.z), "f"(ah.w) : "memory");
}

extern "C" void kernel_launch(void* const* d_in, const int* in_sizes, int n_in,
                              void* d_out, int out_size)
{
    const float* x   = (const float*)d_in[0];   // [16, 64, 32768] float32
    const int*   idx = (const int*)  d_in[1];   // [16, 64] int32
    float*       out = (float*)d_out;           // [16, 1, 32768] float32

    dim3 block(128);
    dim3 grid(NTILES / 2, BATCH);               // (32, 16) = 512 blocks
    sparse_audio_gather<<<grid, block>>>(x, idx, out);
}